// round 6
// baseline (speedup 1.0000x reference)
#include <cuda_runtime.h>
#include <cstdio>
#include <cstdlib>

#define N_NODES   50000
#define N_EDGES   1250000
#define EMBED     64
#define HIDDEN    64
#define NUM_REL   3
#define N_GRAPHS  512
#define N_CLASSES 2

#define NBINS (N_NODES * NUM_REL)            // 150000
#define AGG_FLOATS (N_NODES * NUM_REL * 64)  // 9,600,000

// ---------------- scratch (static device globals; no allocation) ----------------
// NOTE: these are ONLY touched through real device addresses (cudaGetSymbolAddress)
// or direct symbol references inside kernels. Passing the symbol name as a kernel
// argument from host passes the HOST shadow address — which GB300's ATS happily
// dereferences into host memory (zeros) with no fault. That was rounds 0-5's bug.
__device__ __align__(16) float g_h0[N_NODES * 64];
__device__ __align__(16) float g_h1[N_NODES * 64];
__device__ __align__(16) float g_agg[AGG_FLOATS];
__device__ __align__(16) float g_inv[NBINS];
__device__ int   g_cnt[NBINS];
__device__ int   g_maxA;
__device__ int   g_xsel;      // 1 -> candA is x, 0 -> candA is batch

// ---------------- init / classification ----------------
__global__ void init_kernel() {
    int i = blockIdx.x * blockDim.x + threadIdx.x;
    if (i < NBINS) g_cnt[i] = 0;
    if (i == 0) g_maxA = 0;
}

__global__ void classify_kernel(const int* __restrict__ A) {
    int i = blockIdx.x * blockDim.x + threadIdx.x;
    int m = 0;
    for (; i < N_NODES; i += gridDim.x * blockDim.x) m = max(m, A[i]);
    for (int o = 16; o > 0; o >>= 1) m = max(m, __shfl_down_sync(0xffffffffu, m, o));
    if ((threadIdx.x & 31) == 0) atomicMax(&g_maxA, m);
}

__global__ void setflag_kernel() {
    g_xsel = (g_maxA >= N_GRAPHS) ? 1 : 0;   // batch < 512; x ranges to ~50000
}

// ---------------- pipeline kernels ----------------
__global__ void zero_agg_kernel() {
    int i = blockIdx.x * blockDim.x + threadIdx.x;
    if (i < AGG_FLOATS / 4)
        reinterpret_cast<float4*>(g_agg)[i] = make_float4(0.f, 0.f, 0.f, 0.f);
}

__global__ void count_kernel(const int* __restrict__ dst, const int* __restrict__ et) {
    int e = blockIdx.x * blockDim.x + threadIdx.x;
    if (e < N_EDGES)
        atomicAdd(&g_cnt[dst[e] * NUM_REL + et[e]], 1);
}

__global__ void inv_kernel() {
    int i = blockIdx.x * blockDim.x + threadIdx.x;
    if (i < NBINS) g_inv[i] = 1.0f / (float)max(g_cnt[i], 1);
}

// h0[n] = (x[n]==0) ? 0 : emb[x[n]]   (padding_idx = 0)
__global__ void embed_kernel(const int* __restrict__ candA, const int* __restrict__ candB,
                             const float* __restrict__ emb) {
    const int* x = g_xsel ? candA : candB;
    int i = blockIdx.x * blockDim.x + threadIdx.x;
    if (i >= N_NODES * 16) return;
    int n = i >> 4, q = i & 15;
    int tok = x[n];
    float4 v = make_float4(0.f, 0.f, 0.f, 0.f);
    if (tok != 0) v = reinterpret_cast<const float4*>(emb)[tok * 16 + q];
    reinterpret_cast<float4*>(g_h0)[i] = v;
}

// agg[dst][rel] += h[src]: 16 lanes/edge, float4 vector reduction (no return)
__global__ void scatter_kernel(const float* __restrict__ hin,
                               const int* __restrict__ src,
                               const int* __restrict__ dst,
                               const int* __restrict__ et) {
    long long idx = (long long)blockIdx.x * blockDim.x + threadIdx.x;
    if (idx >= (long long)N_EDGES * 16) return;
    int e = (int)(idx >> 4), lane = (int)(idx & 15);
    int s = src[e], d = dst[e], r = et[e];
    float4 v = reinterpret_cast<const float4*>(hin)[s * 16 + lane];
    float* p = &g_agg[((d * NUM_REL + r) << 6) + (lane << 2)];
    asm volatile("red.global.add.v4.f32 [%0], {%1,%2,%3,%4};"
                 :: "l"(p), "f"(v.x), "f"(v.y), "f"(v.z), "f"(v.w) : "memory");
}

// hout[n] = relu( bias + h[n]@Wroot + sum_r (agg[n][r]*inv[n][r]) @ Wrel[r] )
// A[50000x256] @ B[256x64]; 128-node x 64-feat tile; 8x4 register block.
#define TK 32
__global__ __launch_bounds__(256)
void transform_kernel(const float* __restrict__ hin,
                      const float* __restrict__ wroot,
                      const float* __restrict__ wrel,
                      const float* __restrict__ bias,
                      float* __restrict__ hout) {
    __shared__ float Bs[TK * 64];
    __shared__ float As[TK * 128];

    int t  = threadIdx.x;
    int tx = t & 15;
    int ty = t >> 4;
    int n0 = blockIdx.x * 128;
    int n_l = t & 127;
    int kh  = t >> 7;
    int n   = n0 + n_l;
    bool in_range = (n < N_NODES);

    float4 acc[8];
#pragma unroll
    for (int i = 0; i < 8; i++) acc[i] = make_float4(0.f, 0.f, 0.f, 0.f);

    for (int c = 0; c < 256 / TK; c++) {
        int k0 = c * TK;
        __syncthreads();
        {
            float4* Bs4 = reinterpret_cast<float4*>(Bs);
            const float4* r4 = reinterpret_cast<const float4*>(wroot);
            const float4* w4 = reinterpret_cast<const float4*>(wrel);
#pragma unroll
            for (int j = 0; j < 2; j++) {
                int q  = t + 256 * j;
                int kg = k0 + (q >> 4);
                int fq = q & 15;
                Bs4[q] = (kg < 64) ? r4[kg * 16 + fq] : w4[(kg - 64) * 16 + fq];
            }
        }
        {
            int kb = kh * 16;
#pragma unroll
            for (int j = 0; j < 4; j++) {
                int kg = k0 + kb + 4 * j;
                float4 v = make_float4(0.f, 0.f, 0.f, 0.f);
                if (in_range) {
                    if (kg < 64) {
                        v = *reinterpret_cast<const float4*>(&hin[n * 64 + kg]);
                    } else {
                        int r  = (kg >> 6) - 1;
                        int kk = kg & 63;
                        v = *reinterpret_cast<const float4*>(
                                &g_agg[(n * NUM_REL + r) * 64 + kk]);
                        float iv = g_inv[n * NUM_REL + r];
                        v.x *= iv; v.y *= iv; v.z *= iv; v.w *= iv;
                    }
                }
                As[(kb + 4 * j + 0) * 128 + n_l] = v.x;
                As[(kb + 4 * j + 1) * 128 + n_l] = v.y;
                As[(kb + 4 * j + 2) * 128 + n_l] = v.z;
                As[(kb + 4 * j + 3) * 128 + n_l] = v.w;
            }
        }
        __syncthreads();

        const float4* Bs4 = reinterpret_cast<const float4*>(Bs);
#pragma unroll
        for (int k = 0; k < TK; k++) {
            float4 w = Bs4[k * 16 + tx];
#pragma unroll
            for (int i = 0; i < 8; i++) {
                float a = As[k * 128 + ty * 8 + i];
                acc[i].x += a * w.x;
                acc[i].y += a * w.y;
                acc[i].z += a * w.z;
                acc[i].w += a * w.w;
            }
        }
    }

    float4 b4 = *reinterpret_cast<const float4*>(&bias[tx * 4]);
#pragma unroll
    for (int i = 0; i < 8; i++) {
        int nn = n0 + ty * 8 + i;
        if (nn < N_NODES) {
            float4 o;
            o.x = fmaxf(acc[i].x + b4.x, 0.f);
            o.y = fmaxf(acc[i].y + b4.y, 0.f);
            o.z = fmaxf(acc[i].z + b4.z, 0.f);
            o.w = fmaxf(acc[i].w + b4.w, 0.f);
            *reinterpret_cast<float4*>(&hout[nn * 64 + tx * 4]) = o;
        }
    }
}

// batch is sorted: binary-search per-graph bounds, mean, tiny linear.
__global__ void pool_kernel(const float* __restrict__ h,
                            const int* __restrict__ candA,
                            const int* __restrict__ candB,
                            const float* __restrict__ lin_w,
                            const float* __restrict__ lin_b,
                            float* __restrict__ out) {
    const int* batch = g_xsel ? candB : candA;
    int g = blockIdx.x;
    int f = threadIdx.x;
    __shared__ int bounds[2];
    __shared__ float mean_s[64];

    if (f < 2) {
        int v = g + f;
        int lo = 0, hi = N_NODES;
        while (lo < hi) {
            int m = (lo + hi) >> 1;
            if (batch[m] < v) lo = m + 1; else hi = m;
        }
        bounds[f] = lo;
    }
    __syncthreads();
    int s = bounds[0], e = bounds[1];

    float acc = 0.f;
    for (int i = s; i < e; i++) acc += h[i * 64 + f];
    float cnt = (float)(e - s);
    mean_s[f] = acc / fmaxf(cnt, 1.f);
    __syncthreads();

    if (f < N_CLASSES) {
        float o = lin_b[f];
#pragma unroll
        for (int k = 0; k < 64; k++) o += mean_s[k] * lin_w[k * N_CLASSES + f];
        out[g * N_CLASSES + f] = o;
    }
}

// ---------------- launch ----------------
extern "C" void kernel_launch(void* const* d_in, const int* in_sizes, int n_in,
                              void* d_out, int out_size) {
    // real device addresses for the scratch symbols (host API; capture-safe)
    float *h0p = nullptr, *h1p = nullptr;
    cudaGetSymbolAddress((void**)&h0p, g_h0);
    cudaGetSymbolAddress((void**)&h1p, g_h1);
    if (!h0p || !h1p) { fprintf(stderr, "HXH symbol addr failed\n"); abort(); }

    // size-based input dispatch (verified: dict order, element counts)
    const void* pA50k = nullptr;  const void* pB50k = nullptr;
    const void* p_eidx = nullptr; const void* p_et = nullptr;
    const void* p_emb = nullptr;
    const void* p_rel[2]  = {nullptr, nullptr};
    const void* p_root[2] = {nullptr, nullptr};
    const void* p_b[2]    = {nullptr, nullptr};
    const void* p_linw = nullptr; const void* p_linb = nullptr;
    int n_rel = 0, n_root = 0, n_b = 0;

    for (int i = 0; i < n_in; i++) {
        int sz = in_sizes[i];
        const void* p = d_in[i];
        switch (sz) {
            case 2 * N_EDGES:       p_eidx = p; break;
            case N_EDGES:           p_et = p; break;
            case 50000 * EMBED:     p_emb = p; break;
            case NUM_REL * 64 * 64: if (n_rel < 2)  p_rel[n_rel++] = p;   break;
            case 64 * 64:           if (n_root < 2) p_root[n_root++] = p; break;
            case 64:                if (n_b < 2)    p_b[n_b++] = p;       break;
            case 64 * N_CLASSES:    p_linw = p; break;
            case N_CLASSES:         p_linb = p; break;
            case N_NODES:           if (!pA50k) pA50k = p; else pB50k = p; break;
            default: break;
        }
    }

    bool ok = pA50k && pB50k && p_eidx && p_et && p_emb &&
              n_rel == 2 && n_root == 2 && n_b == 2 && p_linw && p_linb;
    if (!ok) { fprintf(stderr, "HXH size-match failed\n"); fflush(stderr); abort(); }

    const int*   candA   = (const int*)pA50k;
    const int*   candB   = (const int*)pB50k;
    const int*   src     = (const int*)p_eidx;
    const int*   dst     = (const int*)p_eidx + N_EDGES;
    const int*   et      = (const int*)p_et;
    const float* emb     = (const float*)p_emb;
    const float* w1_rel  = (const float*)p_rel[0];
    const float* w2_rel  = (const float*)p_rel[1];
    const float* w1_root = (const float*)p_root[0];
    const float* w2_root = (const float*)p_root[1];
    const float* b1      = (const float*)p_b[0];
    const float* b2      = (const float*)p_b[1];
    const float* lin_w   = (const float*)p_linw;
    const float* lin_b   = (const float*)p_linb;
    float* out = (float*)d_out;

    const int T = 256;

    // x/batch disambiguation + structure counts (shared by both layers)
    init_kernel<<<(NBINS + T - 1) / T, T>>>();
    classify_kernel<<<64, T>>>(candA);
    setflag_kernel<<<1, 1>>>();
    count_kernel<<<(N_EDGES + T - 1) / T, T>>>(dst, et);
    inv_kernel<<<(NBINS + T - 1) / T, T>>>();

    // embedding -> g_h0
    embed_kernel<<<(N_NODES * 16 + T - 1) / T, T>>>(candA, candB, emb);

    // ---- layer 1 ----
    zero_agg_kernel<<<(AGG_FLOATS / 4 + T - 1) / T, T>>>();
    scatter_kernel<<<(N_EDGES * 16 + T - 1) / T, T>>>(h0p, src, dst, et);
    transform_kernel<<<(N_NODES + 127) / 128, 256>>>(h0p, w1_root, w1_rel, b1, h1p);

    // ---- layer 2 ----
    zero_agg_kernel<<<(AGG_FLOATS / 4 + T - 1) / T, T>>>();
    scatter_kernel<<<(N_EDGES * 16 + T - 1) / T, T>>>(h1p, src, dst, et);
    transform_kernel<<<(N_NODES + 127) / 128, 256>>>(h1p, w2_root, w2_rel, b2, h0p);

    // ---- pool + classify ----
    pool_kernel<<<N_GRAPHS, 64>>>(h0p, candA, candB, lin_w, lin_b, out);
}

// round 7
// speedup vs baseline: 1.2951x; 1.2951x over previous
#include <cuda_runtime.h>
#include <cstdio>
#include <cstdlib>

#define N_NODES   50000
#define N_EDGES   1250000
#define EMBED     64
#define HIDDEN    64
#define NUM_REL   3
#define N_GRAPHS  512
#define N_CLASSES 2

#define NBINS (N_NODES * NUM_REL)            // 150000
#define AGG_FLOATS (N_NODES * NUM_REL * 64)  // 9,600,000
#define SCAN_B 1024
#define SCAN_NB ((NBINS + SCAN_B - 1) / SCAN_B)   // 147

// ---------------- scratch (device globals; addresses resolved via cudaGetSymbolAddress) ----------------
__device__ __align__(16) float g_h0[N_NODES * 64];
__device__ __align__(16) float g_h1[N_NODES * 64];
__device__ __align__(16) float g_agg[AGG_FLOATS];
__device__ __align__(16) float g_inv[NBINS];
__device__ int   g_cnt[NBINS];
__device__ int   g_off[NBINS + 1];
__device__ int   g_cur[NBINS];
__device__ int   g_bsum[SCAN_NB + 1];
__device__ int   g_eord[N_EDGES];     // src ids sorted by (dst,rel) bin
__device__ int   g_maxA;
__device__ int   g_xsel;              // 1 -> candA is x, 0 -> candA is batch

// ---------------- init / classification ----------------
__global__ void init_kernel() {
    int i = blockIdx.x * blockDim.x + threadIdx.x;
    if (i < NBINS) g_cnt[i] = 0;
    if (i == 0) g_maxA = 0;
}

__global__ void classify_kernel(const int* __restrict__ A) {
    int i = blockIdx.x * blockDim.x + threadIdx.x;
    int m = 0;
    for (; i < N_NODES; i += gridDim.x * blockDim.x) m = max(m, A[i]);
    for (int o = 16; o > 0; o >>= 1) m = max(m, __shfl_down_sync(0xffffffffu, m, o));
    if ((threadIdx.x & 31) == 0) atomicMax(&g_maxA, m);
}

__global__ void setflag_kernel() {
    g_xsel = (g_maxA >= N_GRAPHS) ? 1 : 0;
}

// ---------------- degree counts + CSR build ----------------
__global__ void count_kernel(const int* __restrict__ dst, const int* __restrict__ et) {
    int e = blockIdx.x * blockDim.x + threadIdx.x;
    if (e < N_EDGES)
        atomicAdd(&g_cnt[dst[e] * NUM_REL + et[e]], 1);
}

__global__ void inv_kernel() {
    int i = blockIdx.x * blockDim.x + threadIdx.x;
    if (i < NBINS) g_inv[i] = 1.0f / (float)max(g_cnt[i], 1);
}

// block-local exclusive scan of g_cnt -> g_off (local), block totals -> g_bsum
__global__ __launch_bounds__(SCAN_B)
void scan1_kernel() {
    __shared__ int wsum[32];
    int i = blockIdx.x * SCAN_B + threadIdx.x;
    int lane = threadIdx.x & 31, wid = threadIdx.x >> 5;
    int c = (i < NBINS) ? g_cnt[i] : 0;
    int v = c;
#pragma unroll
    for (int o = 1; o < 32; o <<= 1) {
        int u = __shfl_up_sync(0xffffffffu, v, o);
        if (lane >= o) v += u;
    }
    if (lane == 31) wsum[wid] = v;
    __syncthreads();
    if (wid == 0) {
        int w = wsum[lane];
        int s = w;
#pragma unroll
        for (int o = 1; o < 32; o <<= 1) {
            int u = __shfl_up_sync(0xffffffffu, s, o);
            if (lane >= o) s += u;
        }
        wsum[lane] = s - w;     // exclusive warp-prefix
        if (lane == 31 && i / SCAN_B == blockIdx.x) g_bsum[blockIdx.x] = s;  // block total
    }
    __syncthreads();
    int excl = v - c + wsum[wid];
    if (i < NBINS) g_off[i] = excl;
}

// serial scan of the 147 block totals (single thread; trivial size)
__global__ void scan2_kernel() {
    if (threadIdx.x || blockIdx.x) return;
    int acc = 0;
    for (int j = 0; j < SCAN_NB; j++) {
        int t = g_bsum[j];
        g_bsum[j] = acc;
        acc += t;
    }
    g_bsum[SCAN_NB] = acc;
}

// fixup: add block prefix; init cursors; store total
__global__ void scan3_kernel() {
    int i = blockIdx.x * blockDim.x + threadIdx.x;
    if (i < NBINS) {
        int off = g_off[i] + g_bsum[i / SCAN_B];
        g_off[i] = off;
        g_cur[i] = off;
    }
    if (i == 0) g_off[NBINS] = g_bsum[SCAN_NB];
}

// counting-sort placement: g_eord[pos] = src, grouped by bin
__global__ void place_kernel(const int* __restrict__ src,
                             const int* __restrict__ dst,
                             const int* __restrict__ et) {
    int e = blockIdx.x * blockDim.x + threadIdx.x;
    if (e >= N_EDGES) return;
    int bin = dst[e] * NUM_REL + et[e];
    int pos = atomicAdd(&g_cur[bin], 1);
    g_eord[pos] = src[e];
}

// ---------------- embedding ----------------
__global__ void embed_kernel(const int* __restrict__ candA, const int* __restrict__ candB,
                             const float* __restrict__ emb) {
    const int* x = g_xsel ? candA : candB;
    int i = blockIdx.x * blockDim.x + threadIdx.x;
    if (i >= N_NODES * 16) return;
    int n = i >> 4, q = i & 15;
    int tok = x[n];
    float4 v = make_float4(0.f, 0.f, 0.f, 0.f);
    if (tok != 0) v = reinterpret_cast<const float4*>(emb)[tok * 16 + q];
    reinterpret_cast<float4*>(g_h0)[i] = v;
}

// ---------------- aggregation: CSR gather, atomic-free ----------------
// g_agg[bin] = inv[bin] * sum_{e in bin} h[src_e];  16 lanes x float4 per bin.
__global__ __launch_bounds__(256)
void agg_kernel(const float* __restrict__ hin) {
    int b = blockIdx.x * 16 + (threadIdx.x >> 4);
    if (b >= NBINS) return;
    int lane = threadIdx.x & 15;
    int i  = g_off[b];
    int s1 = g_off[b + 1];

    float4 acc = make_float4(0.f, 0.f, 0.f, 0.f);
    const float4* h4 = reinterpret_cast<const float4*>(hin);

    // 2-wide software pipeline for MLP
    for (; i + 1 < s1; i += 2) {
        int sa = g_eord[i];
        int sb = g_eord[i + 1];
        float4 va = h4[sa * 16 + lane];
        float4 vb = h4[sb * 16 + lane];
        acc.x += va.x + vb.x;
        acc.y += va.y + vb.y;
        acc.z += va.z + vb.z;
        acc.w += va.w + vb.w;
    }
    if (i < s1) {
        float4 va = h4[g_eord[i] * 16 + lane];
        acc.x += va.x; acc.y += va.y; acc.z += va.z; acc.w += va.w;
    }

    float iv = g_inv[b];
    acc.x *= iv; acc.y *= iv; acc.z *= iv; acc.w *= iv;
    reinterpret_cast<float4*>(g_agg)[b * 16 + lane] = acc;
}

// ---------------- node transform (agg already mean-scaled) ----------------
#define TK 32
__global__ __launch_bounds__(256)
void transform_kernel(const float* __restrict__ hin,
                      const float* __restrict__ wroot,
                      const float* __restrict__ wrel,
                      const float* __restrict__ bias,
                      float* __restrict__ hout) {
    __shared__ float Bs[TK * 64];
    __shared__ float As[TK * 128];

    int t  = threadIdx.x;
    int tx = t & 15;
    int ty = t >> 4;
    int n0 = blockIdx.x * 128;
    int n_l = t & 127;
    int kh  = t >> 7;
    int n   = n0 + n_l;
    bool in_range = (n < N_NODES);

    float4 acc[8];
#pragma unroll
    for (int i = 0; i < 8; i++) acc[i] = make_float4(0.f, 0.f, 0.f, 0.f);

    for (int c = 0; c < 256 / TK; c++) {
        int k0 = c * TK;
        __syncthreads();
        {
            float4* Bs4 = reinterpret_cast<float4*>(Bs);
            const float4* r4 = reinterpret_cast<const float4*>(wroot);
            const float4* w4 = reinterpret_cast<const float4*>(wrel);
#pragma unroll
            for (int j = 0; j < 2; j++) {
                int q  = t + 256 * j;
                int kg = k0 + (q >> 4);
                int fq = q & 15;
                Bs4[q] = (kg < 64) ? r4[kg * 16 + fq] : w4[(kg - 64) * 16 + fq];
            }
        }
        {
            int kb = kh * 16;
#pragma unroll
            for (int j = 0; j < 4; j++) {
                int kg = k0 + kb + 4 * j;
                float4 v = make_float4(0.f, 0.f, 0.f, 0.f);
                if (in_range) {
                    if (kg < 64) {
                        v = *reinterpret_cast<const float4*>(&hin[n * 64 + kg]);
                    } else {
                        int r  = (kg >> 6) - 1;
                        int kk = kg & 63;
                        v = *reinterpret_cast<const float4*>(
                                &g_agg[(n * NUM_REL + r) * 64 + kk]);
                    }
                }
                As[(kb + 4 * j + 0) * 128 + n_l] = v.x;
                As[(kb + 4 * j + 1) * 128 + n_l] = v.y;
                As[(kb + 4 * j + 2) * 128 + n_l] = v.z;
                As[(kb + 4 * j + 3) * 128 + n_l] = v.w;
            }
        }
        __syncthreads();

        const float4* Bs4 = reinterpret_cast<const float4*>(Bs);
#pragma unroll
        for (int k = 0; k < TK; k++) {
            float4 w = Bs4[k * 16 + tx];
#pragma unroll
            for (int i = 0; i < 8; i++) {
                float a = As[k * 128 + ty * 8 + i];
                acc[i].x += a * w.x;
                acc[i].y += a * w.y;
                acc[i].z += a * w.z;
                acc[i].w += a * w.w;
            }
        }
    }

    float4 b4 = *reinterpret_cast<const float4*>(&bias[tx * 4]);
#pragma unroll
    for (int i = 0; i < 8; i++) {
        int nn = n0 + ty * 8 + i;
        if (nn < N_NODES) {
            float4 o;
            o.x = fmaxf(acc[i].x + b4.x, 0.f);
            o.y = fmaxf(acc[i].y + b4.y, 0.f);
            o.z = fmaxf(acc[i].z + b4.z, 0.f);
            o.w = fmaxf(acc[i].w + b4.w, 0.f);
            *reinterpret_cast<float4*>(&hout[nn * 64 + tx * 4]) = o;
        }
    }
}

// ---------------- pooling + classifier ----------------
__global__ void pool_kernel(const float* __restrict__ h,
                            const int* __restrict__ candA,
                            const int* __restrict__ candB,
                            const float* __restrict__ lin_w,
                            const float* __restrict__ lin_b,
                            float* __restrict__ out) {
    const int* batch = g_xsel ? candB : candA;
    int g = blockIdx.x;
    int f = threadIdx.x;
    __shared__ int bounds[2];
    __shared__ float mean_s[64];

    if (f < 2) {
        int v = g + f;
        int lo = 0, hi = N_NODES;
        while (lo < hi) {
            int m = (lo + hi) >> 1;
            if (batch[m] < v) lo = m + 1; else hi = m;
        }
        bounds[f] = lo;
    }
    __syncthreads();
    int s = bounds[0], e = bounds[1];

    float acc = 0.f;
    for (int i = s; i < e; i++) acc += h[i * 64 + f];
    float cnt = (float)(e - s);
    mean_s[f] = acc / fmaxf(cnt, 1.f);
    __syncthreads();

    if (f < N_CLASSES) {
        float o = lin_b[f];
#pragma unroll
        for (int k = 0; k < 64; k++) o += mean_s[k] * lin_w[k * N_CLASSES + f];
        out[g * N_CLASSES + f] = o;
    }
}

// ---------------- launch ----------------
extern "C" void kernel_launch(void* const* d_in, const int* in_sizes, int n_in,
                              void* d_out, int out_size) {
    float *h0p = nullptr, *h1p = nullptr;
    cudaGetSymbolAddress((void**)&h0p, g_h0);
    cudaGetSymbolAddress((void**)&h1p, g_h1);
    if (!h0p || !h1p) { fprintf(stderr, "HXH symbol addr failed\n"); abort(); }

    const void* pA50k = nullptr;  const void* pB50k = nullptr;
    const void* p_eidx = nullptr; const void* p_et = nullptr;
    const void* p_emb = nullptr;
    const void* p_rel[2]  = {nullptr, nullptr};
    const void* p_root[2] = {nullptr, nullptr};
    const void* p_b[2]    = {nullptr, nullptr};
    const void* p_linw = nullptr; const void* p_linb = nullptr;
    int n_rel = 0, n_root = 0, n_b = 0;

    for (int i = 0; i < n_in; i++) {
        int sz = in_sizes[i];
        const void* p = d_in[i];
        switch (sz) {
            case 2 * N_EDGES:       p_eidx = p; break;
            case N_EDGES:           p_et = p; break;
            case 50000 * EMBED:     p_emb = p; break;
            case NUM_REL * 64 * 64: if (n_rel < 2)  p_rel[n_rel++] = p;   break;
            case 64 * 64:           if (n_root < 2) p_root[n_root++] = p; break;
            case 64:                if (n_b < 2)    p_b[n_b++] = p;       break;
            case 64 * N_CLASSES:    p_linw = p; break;
            case N_CLASSES:         p_linb = p; break;
            case N_NODES:           if (!pA50k) pA50k = p; else pB50k = p; break;
            default: break;
        }
    }

    bool ok = pA50k && pB50k && p_eidx && p_et && p_emb &&
              n_rel == 2 && n_root == 2 && n_b == 2 && p_linw && p_linb;
    if (!ok) { fprintf(stderr, "HXH size-match failed\n"); fflush(stderr); abort(); }

    const int*   candA   = (const int*)pA50k;
    const int*   candB   = (const int*)pB50k;
    const int*   src     = (const int*)p_eidx;
    const int*   dst     = (const int*)p_eidx + N_EDGES;
    const int*   et      = (const int*)p_et;
    const float* emb     = (const float*)p_emb;
    const float* w1_rel  = (const float*)p_rel[0];
    const float* w2_rel  = (const float*)p_rel[1];
    const float* w1_root = (const float*)p_root[0];
    const float* w2_root = (const float*)p_root[1];
    const float* b1      = (const float*)p_b[0];
    const float* b2      = (const float*)p_b[1];
    const float* lin_w   = (const float*)p_linw;
    const float* lin_b   = (const float*)p_linb;
    float* out = (float*)d_out;

    const int T = 256;

    // disambiguate x/batch + per-bin degree counts
    init_kernel<<<(NBINS + T - 1) / T, T>>>();
    classify_kernel<<<64, T>>>(candA);
    setflag_kernel<<<1, 1>>>();
    count_kernel<<<(N_EDGES + T - 1) / T, T>>>(dst, et);
    inv_kernel<<<(NBINS + T - 1) / T, T>>>();

    // CSR build (structure shared by both layers)
    scan1_kernel<<<SCAN_NB, SCAN_B>>>();
    scan2_kernel<<<1, 32>>>();
    scan3_kernel<<<(NBINS + T - 1) / T, T>>>();
    place_kernel<<<(N_EDGES + T - 1) / T, T>>>(src, dst, et);

    // embedding -> g_h0 (overlaps CSR build in-stream order, both cheap)
    embed_kernel<<<(N_NODES * 16 + T - 1) / T, T>>>(candA, candB, emb);

    // ---- layer 1 ----
    agg_kernel<<<(NBINS + 15) / 16, 256>>>(h0p);
    transform_kernel<<<(N_NODES + 127) / 128, 256>>>(h0p, w1_root, w1_rel, b1, h1p);

    // ---- layer 2 ----
    agg_kernel<<<(NBINS + 15) / 16, 256>>>(h1p);
    transform_kernel<<<(N_NODES + 127) / 128, 256>>>(h1p, w2_root, w2_rel, b2, h0p);

    // ---- pool + classify ----
    pool_kernel<<<N_GRAPHS, 64>>>(h0p, candA, candB, lin_w, lin_b, out);
}

// round 11
// speedup vs baseline: 1.3499x; 1.0423x over previous
#include <cuda_runtime.h>
#include <cuda_bf16.h>
#include <cstdint>
#include <cstdio>
#include <cstdlib>

#define N_NODES   50000
#define N_EDGES   1250000
#define EMBED     64
#define HIDDEN    64
#define NUM_REL   3
#define N_GRAPHS  512
#define N_CLASSES 2

#define NBINS (N_NODES * NUM_REL)            // 150000
#define SCAN_B 1024
#define SCAN_NB ((NBINS + SCAN_B - 1) / SCAN_B)   // 147

#define APF 68        // fp32 smem pitch: 64 + 4 pad

// ---------------- scratch (device globals; ptrs resolved via cudaGetSymbolAddress) ----------------
__device__ __align__(16) float g_h0[N_NODES * 64];     // 12.8 MB
__device__ __align__(16) float g_h1[N_NODES * 64];     // 12.8 MB
__device__ __align__(16) float g_agg[NBINS * 64];      // 38.4 MB
__device__ __align__(16) float g_inv[NBINS];
__device__ int   g_cnt[NBINS];
__device__ int   g_off[NBINS + 1];
__device__ int   g_cur[NBINS];
__device__ int   g_bsum[SCAN_NB + 1];
__device__ int   g_eord[N_EDGES];
__device__ int   g_maxA;
__device__ int   g_xsel;

// ---------------- init / classification ----------------
__global__ void init_kernel() {
    int i = blockIdx.x * blockDim.x + threadIdx.x;
    if (i < NBINS) g_cnt[i] = 0;
    if (i == 0) g_maxA = 0;
}

__global__ void classify_kernel(const int* __restrict__ A) {
    int i = blockIdx.x * blockDim.x + threadIdx.x;
    int m = 0;
    for (; i < N_NODES; i += gridDim.x * blockDim.x) m = max(m, A[i]);
    for (int o = 16; o > 0; o >>= 1) m = max(m, __shfl_down_sync(0xffffffffu, m, o));
    if ((threadIdx.x & 31) == 0) atomicMax(&g_maxA, m);
}

__global__ void setflag_kernel() {
    g_xsel = (g_maxA >= N_GRAPHS) ? 1 : 0;
}

// ---------------- degree counts + CSR build ----------------
__global__ void count_kernel(const int* __restrict__ dst, const int* __restrict__ et) {
    int e = blockIdx.x * blockDim.x + threadIdx.x;
    if (e < N_EDGES)
        atomicAdd(&g_cnt[dst[e] * NUM_REL + et[e]], 1);
}

__global__ void inv_kernel() {
    int i = blockIdx.x * blockDim.x + threadIdx.x;
    if (i < NBINS) g_inv[i] = 1.0f / (float)max(g_cnt[i], 1);
}

__global__ __launch_bounds__(SCAN_B)
void scan1_kernel() {
    __shared__ int wsum[32];
    int i = blockIdx.x * SCAN_B + threadIdx.x;
    int lane = threadIdx.x & 31, wid = threadIdx.x >> 5;
    int c = (i < NBINS) ? g_cnt[i] : 0;
    int v = c;
#pragma unroll
    for (int o = 1; o < 32; o <<= 1) {
        int u = __shfl_up_sync(0xffffffffu, v, o);
        if (lane >= o) v += u;
    }
    if (lane == 31) wsum[wid] = v;
    __syncthreads();
    if (wid == 0) {
        int w = wsum[lane];
        int s = w;
#pragma unroll
        for (int o = 1; o < 32; o <<= 1) {
            int u = __shfl_up_sync(0xffffffffu, s, o);
            if (lane >= o) s += u;
        }
        wsum[lane] = s - w;
        if (lane == 31) g_bsum[blockIdx.x] = s;
    }
    __syncthreads();
    int excl = v - c + wsum[wid];
    if (i < NBINS) g_off[i] = excl;
}

__global__ void scan2_kernel() {
    if (threadIdx.x || blockIdx.x) return;
    int acc = 0;
    for (int j = 0; j < SCAN_NB; j++) {
        int t = g_bsum[j];
        g_bsum[j] = acc;
        acc += t;
    }
    g_bsum[SCAN_NB] = acc;
}

__global__ void scan3_kernel() {
    int i = blockIdx.x * blockDim.x + threadIdx.x;
    if (i < NBINS) {
        int off = g_off[i] + g_bsum[i / SCAN_B];
        g_off[i] = off;
        g_cur[i] = off;
    }
    if (i == 0) g_off[NBINS] = g_bsum[SCAN_NB];
}

__global__ void place_kernel(const int* __restrict__ src,
                             const int* __restrict__ dst,
                             const int* __restrict__ et) {
    int e = blockIdx.x * blockDim.x + threadIdx.x;
    if (e >= N_EDGES) return;
    int bin = dst[e] * NUM_REL + et[e];
    int pos = atomicAdd(&g_cur[bin], 1);
    g_eord[pos] = src[e];
}

// ---------------- embedding (fp32) ----------------
__global__ void embed_kernel(const int* __restrict__ candA, const int* __restrict__ candB,
                             const float* __restrict__ emb) {
    const int* x = g_xsel ? candA : candB;
    int i = blockIdx.x * blockDim.x + threadIdx.x;   // n*16 + quad
    if (i >= N_NODES * 16) return;
    int n = i >> 4, q = i & 15;
    int tok = x[n];
    float4 v = make_float4(0.f, 0.f, 0.f, 0.f);
    if (tok != 0) v = reinterpret_cast<const float4*>(emb)[tok * 16 + q];
    reinterpret_cast<float4*>(g_h0)[i] = v;
}

// ---------------- aggregation: CSR gather, fp32 ----------------
__global__ __launch_bounds__(256)
void agg_kernel(const float* __restrict__ hin) {
    int b = blockIdx.x * 16 + (threadIdx.x >> 4);
    if (b >= NBINS) return;
    int lane = threadIdx.x & 15;
    int i  = g_off[b];
    int s1 = g_off[b + 1];

    float4 acc = make_float4(0.f, 0.f, 0.f, 0.f);
    const float4* h4 = reinterpret_cast<const float4*>(hin);

    for (; i + 1 < s1; i += 2) {
        float4 va = h4[g_eord[i] * 16 + lane];
        float4 vb = h4[g_eord[i + 1] * 16 + lane];
        acc.x += va.x + vb.x;
        acc.y += va.y + vb.y;
        acc.z += va.z + vb.z;
        acc.w += va.w + vb.w;
    }
    if (i < s1) {
        float4 va = h4[g_eord[i] * 16 + lane];
        acc.x += va.x; acc.y += va.y; acc.z += va.z; acc.w += va.w;
    }

    float iv = g_inv[b];
    acc.x *= iv; acc.y *= iv; acc.z *= iv; acc.w *= iv;
    reinterpret_cast<float4*>(g_agg)[b * 16 + lane] = acc;
}

// ---------------- tf32 helper ----------------
__device__ __forceinline__ uint32_t f2tf32(float f) {
    uint32_t r;
    asm("cvt.rna.tf32.f32 %0, %1;" : "=r"(r) : "f"(f));
    return r;
}

// ---------------- node transform: tf32 mma.sync, fp32 accum ----------------
// hout[n] = relu(bias + [h | agg_r0 | agg_r1 | agg_r2](K=256) @ Wstack)
// Block: 128 nodes x 64 out; 8 warps 4(m) x 2(n); warp tile 32x32; K in 4 chunks of 64.
__global__ __launch_bounds__(256)
void transform_mma_kernel(const float* __restrict__ hin,
                          const float* __restrict__ wroot,
                          const float* __restrict__ wrel,
                          const float* __restrict__ bias,
                          float* __restrict__ hout) {
    extern __shared__ float sm[];
    float* As = sm;                 // 128 x APF (tf32-rounded)
    float* Ws = sm + 128 * APF;     // 64  x APF (W transposed, tf32-rounded)

    int tid  = threadIdx.x;
    int lane = tid & 31, warp = tid >> 5;
    int wm = warp >> 1, wn = warp & 1;
    int g = lane >> 2, t = lane & 3;
    int n0 = blockIdx.x * 128;

    float c[2][4][4];
#pragma unroll
    for (int mt = 0; mt < 2; mt++)
#pragma unroll
        for (int nt = 0; nt < 4; nt++)
#pragma unroll
            for (int j = 0; j < 4; j++) c[mt][nt][j] = 0.f;

    const float4* h4 = reinterpret_cast<const float4*>(hin);
    const float4* a4 = reinterpret_cast<const float4*>(g_agg);

    for (int ch = 0; ch < 4; ch++) {
        __syncthreads();
        // ---- stage A chunk: 128 rows x 64 k (one source per chunk), tf32-rounded ----
#pragma unroll
        for (int it = 0; it < 8; it++) {
            int idx = it * 256 + tid;          // 2048 float4 pieces
            int row = idx >> 4, fq = idx & 15;
            int node = n0 + row;
            float4 v = make_float4(0.f, 0.f, 0.f, 0.f);
            if (node < N_NODES) {
                if (ch == 0) v = h4[node * 16 + fq];
                else         v = a4[(node * 3 + (ch - 1)) * 16 + fq];
            }
            uint32_t* dst = reinterpret_cast<uint32_t*>(&As[row * APF + fq * 4]);
            dst[0] = f2tf32(v.x);
            dst[1] = f2tf32(v.y);
            dst[2] = f2tf32(v.z);
            dst[3] = f2tf32(v.w);
        }
        // ---- stage Ws chunk: 64 n x 64 k (transposed), tf32-rounded ----
#pragma unroll
        for (int it = 0; it < 16; it++) {
            int idx = it * 256 + tid;          // 4096 elements
            int n = idx >> 6, kk = idx & 63;
            float w;
            if (ch == 0) w = wroot[kk * 64 + n];
            else         w = wrel[((ch - 1) * 64 + kk) * 64 + n];
            reinterpret_cast<uint32_t*>(Ws)[n * APF + kk] = f2tf32(w);
        }
        __syncthreads();

        // ---- mma over 8 k8 steps ----
#pragma unroll
        for (int ks = 0; ks < 8; ks++) {
            int kk = ks * 8;
            uint32_t a[2][4], b[4][2];
            const uint32_t* Asu = reinterpret_cast<const uint32_t*>(As);
            const uint32_t* Wsu = reinterpret_cast<const uint32_t*>(Ws);
#pragma unroll
            for (int mt = 0; mt < 2; mt++) {
                int r0 = wm * 32 + mt * 16 + g;
                a[mt][0] = Asu[r0 * APF + kk + t];
                a[mt][1] = Asu[(r0 + 8) * APF + kk + t];
                a[mt][2] = Asu[r0 * APF + kk + t + 4];
                a[mt][3] = Asu[(r0 + 8) * APF + kk + t + 4];
            }
#pragma unroll
            for (int nt = 0; nt < 4; nt++) {
                int cN = wn * 32 + nt * 8 + g;
                b[nt][0] = Wsu[cN * APF + kk + t];
                b[nt][1] = Wsu[cN * APF + kk + t + 4];
            }
#pragma unroll
            for (int mt = 0; mt < 2; mt++)
#pragma unroll
                for (int nt = 0; nt < 4; nt++)
                    asm volatile(
                        "mma.sync.aligned.m16n8k8.row.col.f32.tf32.tf32.f32 "
                        "{%0,%1,%2,%3}, {%4,%5,%6,%7}, {%8,%9}, {%0,%1,%2,%3};"
                        : "+f"(c[mt][nt][0]), "+f"(c[mt][nt][1]),
                          "+f"(c[mt][nt][2]), "+f"(c[mt][nt][3])
                        : "r"(a[mt][0]), "r"(a[mt][1]), "r"(a[mt][2]), "r"(a[mt][3]),
                          "r"(b[nt][0]), "r"(b[nt][1]));
        }
    }

    // ---- epilogue: bias + relu -> fp32 ----
#pragma unroll
    for (int nt = 0; nt < 4; nt++) {
        int col = wn * 32 + nt * 8 + t * 2;
        float bx = bias[col], by = bias[col + 1];
#pragma unroll
        for (int mt = 0; mt < 2; mt++) {
            int r0 = n0 + wm * 32 + mt * 16 + g;
            if (r0 < N_NODES) {
                float2 v = make_float2(fmaxf(c[mt][nt][0] + bx, 0.f),
                                       fmaxf(c[mt][nt][1] + by, 0.f));
                *reinterpret_cast<float2*>(&hout[r0 * 64 + col]) = v;
            }
            int r1 = r0 + 8;
            if (r1 < N_NODES) {
                float2 v = make_float2(fmaxf(c[mt][nt][2] + bx, 0.f),
                                       fmaxf(c[mt][nt][3] + by, 0.f));
                *reinterpret_cast<float2*>(&hout[r1 * 64 + col]) = v;
            }
        }
    }
}

// ---------------- pooling + classifier ----------------
__global__ void pool_kernel(const float* __restrict__ h,
                            const int* __restrict__ candA,
                            const int* __restrict__ candB,
                            const float* __restrict__ lin_w,
                            const float* __restrict__ lin_b,
                            float* __restrict__ out) {
    const int* batch = g_xsel ? candB : candA;
    int g = blockIdx.x;
    int f = threadIdx.x;
    __shared__ int bounds[2];
    __shared__ float mean_s[64];

    if (f < 2) {
        int v = g + f;
        int lo = 0, hi = N_NODES;
        while (lo < hi) {
            int m = (lo + hi) >> 1;
            if (batch[m] < v) lo = m + 1; else hi = m;
        }
        bounds[f] = lo;
    }
    __syncthreads();
    int s = bounds[0], e = bounds[1];

    float acc = 0.f;
    for (int i = s; i < e; i++) acc += h[i * 64 + f];
    float cnt = (float)(e - s);
    mean_s[f] = acc / fmaxf(cnt, 1.f);
    __syncthreads();

    if (f < N_CLASSES) {
        float o = lin_b[f];
#pragma unroll
        for (int k = 0; k < 64; k++) o += mean_s[k] * lin_w[k * N_CLASSES + f];
        out[g * N_CLASSES + f] = o;
    }
}

// ---------------- launch ----------------
extern "C" void kernel_launch(void* const* d_in, const int* in_sizes, int n_in,
                              void* d_out, int out_size) {
    float *h0p = nullptr, *h1p = nullptr;
    cudaGetSymbolAddress((void**)&h0p, g_h0);
    cudaGetSymbolAddress((void**)&h1p, g_h1);
    if (!h0p || !h1p) { fprintf(stderr, "HXH symbol addr failed\n"); abort(); }

    const void* pA50k = nullptr;  const void* pB50k = nullptr;
    const void* p_eidx = nullptr; const void* p_et = nullptr;
    const void* p_emb = nullptr;
    const void* p_rel[2]  = {nullptr, nullptr};
    const void* p_root[2] = {nullptr, nullptr};
    const void* p_b[2]    = {nullptr, nullptr};
    const void* p_linw = nullptr; const void* p_linb = nullptr;
    int n_rel = 0, n_root = 0, n_b = 0;

    for (int i = 0; i < n_in; i++) {
        int sz = in_sizes[i];
        const void* p = d_in[i];
        switch (sz) {
            case 2 * N_EDGES:       p_eidx = p; break;
            case N_EDGES:           p_et = p; break;
            case 50000 * EMBED:     p_emb = p; break;
            case NUM_REL * 64 * 64: if (n_rel < 2)  p_rel[n_rel++] = p;   break;
            case 64 * 64:           if (n_root < 2) p_root[n_root++] = p; break;
            case 64:                if (n_b < 2)    p_b[n_b++] = p;       break;
            case 64 * N_CLASSES:    p_linw = p; break;
            case N_CLASSES:         p_linb = p; break;
            case N_NODES:           if (!pA50k) pA50k = p; else pB50k = p; break;
            default: break;
        }
    }

    bool ok = pA50k && pB50k && p_eidx && p_et && p_emb &&
              n_rel == 2 && n_root == 2 && n_b == 2 && p_linw && p_linb;
    if (!ok) { fprintf(stderr, "HXH size-match failed\n"); fflush(stderr); abort(); }

    const int*   candA   = (const int*)pA50k;
    const int*   candB   = (const int*)pB50k;
    const int*   src     = (const int*)p_eidx;
    const int*   dst     = (const int*)p_eidx + N_EDGES;
    const int*   et      = (const int*)p_et;
    const float* emb     = (const float*)p_emb;
    const float* w1_rel  = (const float*)p_rel[0];
    const float* w2_rel  = (const float*)p_rel[1];
    const float* w1_root = (const float*)p_root[0];
    const float* w2_root = (const float*)p_root[1];
    const float* b1      = (const float*)p_b[0];
    const float* b2      = (const float*)p_b[1];
    const float* lin_w   = (const float*)p_linw;
    const float* lin_b   = (const float*)p_linb;
    float* out = (float*)d_out;

    const int T = 256;
    const int SMEM_X = (128 + 64) * APF * 4;   // 52224 B
    static bool attr_set = false;
    if (!attr_set) {
        cudaFuncSetAttribute(transform_mma_kernel,
                             cudaFuncAttributeMaxDynamicSharedMemorySize, SMEM_X);
        attr_set = true;
    }

    // disambiguate x/batch + degree counts
    init_kernel<<<(NBINS + T - 1) / T, T>>>();
    classify_kernel<<<64, T>>>(candA);
    setflag_kernel<<<1, 1>>>();
    count_kernel<<<(N_EDGES + T - 1) / T, T>>>(dst, et);
    inv_kernel<<<(NBINS + T - 1) / T, T>>>();

    // CSR build
    scan1_kernel<<<SCAN_NB, SCAN_B>>>();
    scan2_kernel<<<1, 32>>>();
    scan3_kernel<<<(NBINS + T - 1) / T, T>>>();
    place_kernel<<<(N_EDGES + T - 1) / T, T>>>(src, dst, et);

    // embedding -> h0
    embed_kernel<<<(N_NODES * 16 + T - 1) / T, T>>>(candA, candB, emb);

    // ---- layer 1 ----
    agg_kernel<<<(NBINS + 15) / 16, 256>>>(h0p);
    transform_mma_kernel<<<(N_NODES + 127) / 128, 256, SMEM_X>>>(h0p, w1_root, w1_rel, b1, h1p);

    // ---- layer 2 ----
    agg_kernel<<<(NBINS + 15) / 16, 256>>>(h1p);
    transform_mma_kernel<<<(N_NODES + 127) / 128, 256, SMEM_X>>>(h1p, w2_root, w2_rel, b2, h0p);

    // ---- pool + classify ----
    pool_kernel<<<N_GRAPHS, 64>>>(h0p, candA, candB, lin_w, lin_b, out);
}

// round 12
// speedup vs baseline: 1.4187x; 1.0509x over previous
#include <cuda_runtime.h>
#include <cuda_fp16.h>
#include <cstdint>
#include <cstdio>
#include <cstdlib>

#define N_NODES   50000
#define N_EDGES   1250000
#define EMBED     64
#define HIDDEN    64
#define NUM_REL   3
#define N_GRAPHS  512
#define N_CLASSES 2

#define NBINS (N_NODES * NUM_REL)            // 150000
#define SCAN_B 1024
#define SCAN_NB ((NBINS + SCAN_B - 1) / SCAN_B)   // 147

#define APF 68        // fp32 smem pitch: 64 + 4 pad

// ---------------- scratch ----------------
__device__ __align__(16) float  g_h0[N_NODES * 64];     // fp32 h (pool path / final)
__device__ __align__(16) __half g_h16a[N_NODES * 64];   // fp16 h copies (gather/staging)
__device__ __align__(16) __half g_h16b[N_NODES * 64];
__device__ __align__(16) __half g_agg16[NBINS * 64];    // fp16 agg (9.6 MB)
__device__ __align__(16) float  g_inv[NBINS];
__device__ int   g_cnt[NBINS];
__device__ int   g_off[NBINS + 1];
__device__ int   g_cur[NBINS];
__device__ int   g_bsum[SCAN_NB + 1];
__device__ int   g_eord[N_EDGES];
__device__ int   g_maxA;   // monotone across replays (BSS 0 -> true max); deterministic
__device__ int   g_xsel;

// ---------------- init + classify (merged) ----------------
__global__ void init_classify_kernel(const int* __restrict__ A, int gsz) {
    int i = blockIdx.x * blockDim.x + threadIdx.x;
    if (i < NBINS) g_cnt[i] = 0;
    int m = 0;
    for (int j = i; j < N_NODES; j += gsz) m = max(m, A[j]);
    for (int o = 16; o > 0; o >>= 1) m = max(m, __shfl_down_sync(0xffffffffu, m, o));
    if ((threadIdx.x & 31) == 0 && m > 0) atomicMax(&g_maxA, m);
}

// ---------------- degree counts + CSR build ----------------
__global__ void count_kernel(const int* __restrict__ dst, const int* __restrict__ et) {
    int e = blockIdx.x * blockDim.x + threadIdx.x;
    if (e < N_EDGES)
        atomicAdd(&g_cnt[dst[e] * NUM_REL + et[e]], 1);
}

// scan1: block-local exclusive scan of cnt + inv computation (folded)
__global__ __launch_bounds__(SCAN_B)
void scan1_kernel() {
    __shared__ int wsum[32];
    int i = blockIdx.x * SCAN_B + threadIdx.x;
    int lane = threadIdx.x & 31, wid = threadIdx.x >> 5;
    int c = (i < NBINS) ? g_cnt[i] : 0;
    if (i < NBINS) g_inv[i] = 1.0f / (float)max(c, 1);
    int v = c;
#pragma unroll
    for (int o = 1; o < 32; o <<= 1) {
        int u = __shfl_up_sync(0xffffffffu, v, o);
        if (lane >= o) v += u;
    }
    if (lane == 31) wsum[wid] = v;
    __syncthreads();
    if (wid == 0) {
        int w = wsum[lane];
        int s = w;
#pragma unroll
        for (int o = 1; o < 32; o <<= 1) {
            int u = __shfl_up_sync(0xffffffffu, s, o);
            if (lane >= o) s += u;
        }
        wsum[lane] = s - w;
        if (lane == 31) g_bsum[blockIdx.x] = s;
    }
    __syncthreads();
    int excl = v - c + wsum[wid];
    if (i < NBINS) g_off[i] = excl;
}

// scan2: serial block-total scan + setflag (folded)
__global__ void scan2_kernel() {
    if (threadIdx.x || blockIdx.x) return;
    int acc = 0;
    for (int j = 0; j < SCAN_NB; j++) {
        int t = g_bsum[j];
        g_bsum[j] = acc;
        acc += t;
    }
    g_bsum[SCAN_NB] = acc;
    g_xsel = (g_maxA >= N_GRAPHS) ? 1 : 0;
}

__global__ void scan3_kernel() {
    int i = blockIdx.x * blockDim.x + threadIdx.x;
    if (i < NBINS) {
        int off = g_off[i] + g_bsum[i / SCAN_B];
        g_off[i] = off;
        g_cur[i] = off;
    }
    if (i == 0) g_off[NBINS] = g_bsum[SCAN_NB];
}

__global__ void place_kernel(const int* __restrict__ src,
                             const int* __restrict__ dst,
                             const int* __restrict__ et) {
    int e = blockIdx.x * blockDim.x + threadIdx.x;
    if (e >= N_EDGES) return;
    int bin = dst[e] * NUM_REL + et[e];
    int pos = atomicAdd(&g_cur[bin], 1);
    g_eord[pos] = src[e];
}

// ---------------- embedding: fp32 table -> fp16 h (+ fp32 not needed for layer-1) ----------------
__global__ void embed_kernel(const int* __restrict__ candA, const int* __restrict__ candB,
                             const float* __restrict__ emb, __half* __restrict__ h16) {
    const int* x = g_xsel ? candA : candB;
    int i = blockIdx.x * blockDim.x + threadIdx.x;   // n*8 + q (8 uint4 of halves per row)
    if (i >= N_NODES * 8) return;
    int n = i >> 3, q = i & 7;
    int tok = x[n];
    uint4 o = make_uint4(0, 0, 0, 0);
    if (tok != 0) {
        const float4* e4 = reinterpret_cast<const float4*>(emb);
        float4 f0 = e4[tok * 16 + q * 2];
        float4 f1 = e4[tok * 16 + q * 2 + 1];
        __half2 h0 = __floats2half2_rn(f0.x, f0.y);
        __half2 h1 = __floats2half2_rn(f0.z, f0.w);
        __half2 h2 = __floats2half2_rn(f1.x, f1.y);
        __half2 h3 = __floats2half2_rn(f1.z, f1.w);
        o.x = *reinterpret_cast<uint32_t*>(&h0);
        o.y = *reinterpret_cast<uint32_t*>(&h1);
        o.z = *reinterpret_cast<uint32_t*>(&h2);
        o.w = *reinterpret_cast<uint32_t*>(&h3);
    }
    reinterpret_cast<uint4*>(h16)[i] = o;
}

// ---------------- aggregation: CSR gather fp16 -> fp32 accum -> fp16 agg ----------------
// 8 lanes per bin (16B = 8 halves each)
__global__ __launch_bounds__(256)
void agg_kernel(const __half* __restrict__ hin16) {
    int b = blockIdx.x * 32 + (threadIdx.x >> 3);
    if (b >= NBINS) return;
    int lane = threadIdx.x & 7;
    int i  = g_off[b];
    int s1 = g_off[b + 1];

    float acc[8] = {0.f, 0.f, 0.f, 0.f, 0.f, 0.f, 0.f, 0.f};
    const uint4* h4 = reinterpret_cast<const uint4*>(hin16);

    for (; i + 1 < s1; i += 2) {
        uint4 va = h4[g_eord[i] * 8 + lane];
        uint4 vb = h4[g_eord[i + 1] * 8 + lane];
        const __half2* pa = reinterpret_cast<const __half2*>(&va);
        const __half2* pb = reinterpret_cast<const __half2*>(&vb);
#pragma unroll
        for (int j = 0; j < 4; j++) {
            float2 fa = __half22float2(pa[j]);
            float2 fb = __half22float2(pb[j]);
            acc[2 * j]     += fa.x + fb.x;
            acc[2 * j + 1] += fa.y + fb.y;
        }
    }
    if (i < s1) {
        uint4 va = h4[g_eord[i] * 8 + lane];
        const __half2* pa = reinterpret_cast<const __half2*>(&va);
#pragma unroll
        for (int j = 0; j < 4; j++) {
            float2 fa = __half22float2(pa[j]);
            acc[2 * j]     += fa.x;
            acc[2 * j + 1] += fa.y;
        }
    }

    float iv = g_inv[b];
    uint4 outv;
    uint32_t* ow = &outv.x;
#pragma unroll
    for (int j = 0; j < 4; j++) {
        __half2 v = __floats2half2_rn(acc[2 * j] * iv, acc[2 * j + 1] * iv);
        ow[j] = *reinterpret_cast<uint32_t*>(&v);
    }
    reinterpret_cast<uint4*>(g_agg16)[b * 8 + lane] = outv;
}

// ---------------- tf32 helper ----------------
__device__ __forceinline__ uint32_t f2tf32(float f) {
    uint32_t r;
    asm("cvt.rna.tf32.f32 %0, %1;" : "=r"(r) : "f"(f));
    return r;
}

// ---------------- node transform: tf32 mma, A staged from fp16 ----------------
// hout = relu(bias + [h | agg_r0 | agg_r1 | agg_r2](K=256) @ Wstack)
// Block 128 x 64; 8 warps 4(m) x 2(n); K in 4 chunks of 64.
__global__ __launch_bounds__(256)
void transform_mma_kernel(const __half* __restrict__ hin16,
                          const float* __restrict__ wroot,
                          const float* __restrict__ wrel,
                          const float* __restrict__ bias,
                          float* __restrict__ hout32,
                          __half* __restrict__ hout16) {
    extern __shared__ float sm[];
    float* As = sm;                 // 128 x APF (tf32)
    float* Ws = sm + 128 * APF;     // 64  x APF (tf32, transposed)

    int tid  = threadIdx.x;
    int lane = tid & 31, warp = tid >> 5;
    int wm = warp >> 1, wn = warp & 1;
    int g = lane >> 2, t = lane & 3;
    int n0 = blockIdx.x * 128;

    float c[2][4][4];
#pragma unroll
    for (int mt = 0; mt < 2; mt++)
#pragma unroll
        for (int nt = 0; nt < 4; nt++)
#pragma unroll
            for (int j = 0; j < 4; j++) c[mt][nt][j] = 0.f;

    const uint4* h4 = reinterpret_cast<const uint4*>(hin16);
    const uint4* a4 = reinterpret_cast<const uint4*>(g_agg16);

    for (int ch = 0; ch < 4; ch++) {
        __syncthreads();
        // ---- stage A chunk from fp16: 128 rows x 64 halves = 1024 uint4 ----
#pragma unroll
        for (int it = 0; it < 4; it++) {
            int idx = it * 256 + tid;
            int row = idx >> 3, hq = idx & 7;
            int node = n0 + row;
            uint4 v = make_uint4(0, 0, 0, 0);
            if (node < N_NODES) {
                if (ch == 0) v = h4[node * 8 + hq];
                else         v = a4[(node * 3 + (ch - 1)) * 8 + hq];
            }
            const __half2* hp = reinterpret_cast<const __half2*>(&v);
            uint32_t* dst = reinterpret_cast<uint32_t*>(&As[row * APF + hq * 8]);
#pragma unroll
            for (int j = 0; j < 4; j++) {
                float2 f = __half22float2(hp[j]);
                dst[2 * j]     = f2tf32(f.x);
                dst[2 * j + 1] = f2tf32(f.y);
            }
        }
        // ---- stage Ws chunk: 64 n x 64 k (transposed), tf32 ----
#pragma unroll
        for (int it = 0; it < 16; it++) {
            int idx = it * 256 + tid;
            int n = idx >> 6, kk = idx & 63;
            float w;
            if (ch == 0) w = wroot[kk * 64 + n];
            else         w = wrel[((ch - 1) * 64 + kk) * 64 + n];
            reinterpret_cast<uint32_t*>(Ws)[n * APF + kk] = f2tf32(w);
        }
        __syncthreads();

        // ---- mma over 8 k8 steps ----
#pragma unroll
        for (int ks = 0; ks < 8; ks++) {
            int kk = ks * 8;
            uint32_t a[2][4], b[4][2];
            const uint32_t* Asu = reinterpret_cast<const uint32_t*>(As);
            const uint32_t* Wsu = reinterpret_cast<const uint32_t*>(Ws);
#pragma unroll
            for (int mt = 0; mt < 2; mt++) {
                int r0 = wm * 32 + mt * 16 + g;
                a[mt][0] = Asu[r0 * APF + kk + t];
                a[mt][1] = Asu[(r0 + 8) * APF + kk + t];
                a[mt][2] = Asu[r0 * APF + kk + t + 4];
                a[mt][3] = Asu[(r0 + 8) * APF + kk + t + 4];
            }
#pragma unroll
            for (int nt = 0; nt < 4; nt++) {
                int cN = wn * 32 + nt * 8 + g;
                b[nt][0] = Wsu[cN * APF + kk + t];
                b[nt][1] = Wsu[cN * APF + kk + t + 4];
            }
#pragma unroll
            for (int mt = 0; mt < 2; mt++)
#pragma unroll
                for (int nt = 0; nt < 4; nt++)
                    asm volatile(
                        "mma.sync.aligned.m16n8k8.row.col.f32.tf32.tf32.f32 "
                        "{%0,%1,%2,%3}, {%4,%5,%6,%7}, {%8,%9}, {%0,%1,%2,%3};"
                        : "+f"(c[mt][nt][0]), "+f"(c[mt][nt][1]),
                          "+f"(c[mt][nt][2]), "+f"(c[mt][nt][3])
                        : "r"(a[mt][0]), "r"(a[mt][1]), "r"(a[mt][2]), "r"(a[mt][3]),
                          "r"(b[nt][0]), "r"(b[nt][1]));
        }
    }

    // ---- epilogue: bias + relu -> fp32 + fp16 ----
#pragma unroll
    for (int nt = 0; nt < 4; nt++) {
        int col = wn * 32 + nt * 8 + t * 2;
        float bx = bias[col], by = bias[col + 1];
#pragma unroll
        for (int mt = 0; mt < 2; mt++) {
            int r0 = n0 + wm * 32 + mt * 16 + g;
            if (r0 < N_NODES) {
                float vx = fmaxf(c[mt][nt][0] + bx, 0.f);
                float vy = fmaxf(c[mt][nt][1] + by, 0.f);
                *reinterpret_cast<float2*>(&hout32[r0 * 64 + col]) = make_float2(vx, vy);
                __half2 hv = __floats2half2_rn(vx, vy);
                *reinterpret_cast<__half2*>(&hout16[r0 * 64 + col]) = hv;
            }
            int r1 = r0 + 8;
            if (r1 < N_NODES) {
                float vx = fmaxf(c[mt][nt][2] + bx, 0.f);
                float vy = fmaxf(c[mt][nt][3] + by, 0.f);
                *reinterpret_cast<float2*>(&hout32[r1 * 64 + col]) = make_float2(vx, vy);
                __half2 hv = __floats2half2_rn(vx, vy);
                *reinterpret_cast<__half2*>(&hout16[r1 * 64 + col]) = hv;
            }
        }
    }
}

// ---------------- pooling + classifier (fp32 h) ----------------
__global__ void pool_kernel(const float* __restrict__ h,
                            const int* __restrict__ candA,
                            const int* __restrict__ candB,
                            const float* __restrict__ lin_w,
                            const float* __restrict__ lin_b,
                            float* __restrict__ out) {
    const int* batch = g_xsel ? candB : candA;
    int g = blockIdx.x;
    int f = threadIdx.x;
    __shared__ int bounds[2];
    __shared__ float mean_s[64];

    if (f < 2) {
        int v = g + f;
        int lo = 0, hi = N_NODES;
        while (lo < hi) {
            int m = (lo + hi) >> 1;
            if (batch[m] < v) lo = m + 1; else hi = m;
        }
        bounds[f] = lo;
    }
    __syncthreads();
    int s = bounds[0], e = bounds[1];

    float acc = 0.f;
    for (int i = s; i < e; i++) acc += h[i * 64 + f];
    float cnt = (float)(e - s);
    mean_s[f] = acc / fmaxf(cnt, 1.f);
    __syncthreads();

    if (f < N_CLASSES) {
        float o = lin_b[f];
#pragma unroll
        for (int k = 0; k < 64; k++) o += mean_s[k] * lin_w[k * N_CLASSES + f];
        out[g * N_CLASSES + f] = o;
    }
}

// ---------------- launch ----------------
extern "C" void kernel_launch(void* const* d_in, const int* in_sizes, int n_in,
                              void* d_out, int out_size) {
    float  *h0p = nullptr;
    __half *ha = nullptr, *hb = nullptr;
    cudaGetSymbolAddress((void**)&h0p, g_h0);
    cudaGetSymbolAddress((void**)&ha, g_h16a);
    cudaGetSymbolAddress((void**)&hb, g_h16b);
    if (!h0p || !ha || !hb) { fprintf(stderr, "HXH symbol addr failed\n"); abort(); }

    const void* pA50k = nullptr;  const void* pB50k = nullptr;
    const void* p_eidx = nullptr; const void* p_et = nullptr;
    const void* p_emb = nullptr;
    const void* p_rel[2]  = {nullptr, nullptr};
    const void* p_root[2] = {nullptr, nullptr};
    const void* p_b[2]    = {nullptr, nullptr};
    const void* p_linw = nullptr; const void* p_linb = nullptr;
    int n_rel = 0, n_root = 0, n_b = 0;

    for (int i = 0; i < n_in; i++) {
        int sz = in_sizes[i];
        const void* p = d_in[i];
        switch (sz) {
            case 2 * N_EDGES:       p_eidx = p; break;
            case N_EDGES:           p_et = p; break;
            case 50000 * EMBED:     p_emb = p; break;
            case NUM_REL * 64 * 64: if (n_rel < 2)  p_rel[n_rel++] = p;   break;
            case 64 * 64:           if (n_root < 2) p_root[n_root++] = p; break;
            case 64:                if (n_b < 2)    p_b[n_b++] = p;       break;
            case 64 * N_CLASSES:    p_linw = p; break;
            case N_CLASSES:         p_linb = p; break;
            case N_NODES:           if (!pA50k) pA50k = p; else pB50k = p; break;
            default: break;
        }
    }

    bool ok = pA50k && pB50k && p_eidx && p_et && p_emb &&
              n_rel == 2 && n_root == 2 && n_b == 2 && p_linw && p_linb;
    if (!ok) { fprintf(stderr, "HXH size-match failed\n"); fflush(stderr); abort(); }

    const int*   candA   = (const int*)pA50k;
    const int*   candB   = (const int*)pB50k;
    const int*   src     = (const int*)p_eidx;
    const int*   dst     = (const int*)p_eidx + N_EDGES;
    const int*   et      = (const int*)p_et;
    const float* emb     = (const float*)p_emb;
    const float* w1_rel  = (const float*)p_rel[0];
    const float* w2_rel  = (const float*)p_rel[1];
    const float* w1_root = (const float*)p_root[0];
    const float* w2_root = (const float*)p_root[1];
    const float* b1      = (const float*)p_b[0];
    const float* b2      = (const float*)p_b[1];
    const float* lin_w   = (const float*)p_linw;
    const float* lin_b   = (const float*)p_linb;
    float* out = (float*)d_out;

    const int T = 256;
    const int SMEM_X = (128 + 64) * APF * 4;   // 52224 B
    static bool attr_set = false;
    if (!attr_set) {
        cudaFuncSetAttribute(transform_mma_kernel,
                             cudaFuncAttributeMaxDynamicSharedMemorySize, SMEM_X);
        attr_set = true;
    }

    const int IC_G = (NBINS + T - 1) / T;
    init_classify_kernel<<<IC_G, T>>>(candA, IC_G * T);
    count_kernel<<<(N_EDGES + T - 1) / T, T>>>(dst, et);
    scan1_kernel<<<SCAN_NB, SCAN_B>>>();
    scan2_kernel<<<1, 32>>>();
    scan3_kernel<<<(NBINS + T - 1) / T, T>>>();
    place_kernel<<<(N_EDGES + T - 1) / T, T>>>(src, dst, et);

    // embedding -> h16a
    embed_kernel<<<(N_NODES * 8 + T - 1) / T, T>>>(candA, candB, emb, ha);

    // ---- layer 1 ----
    agg_kernel<<<(NBINS + 31) / 32, 256>>>(ha);
    transform_mma_kernel<<<(N_NODES + 127) / 128, 256, SMEM_X>>>(ha, w1_root, w1_rel, b1, h0p, hb);

    // ---- layer 2 ----
    agg_kernel<<<(NBINS + 31) / 32, 256>>>(hb);
    transform_mma_kernel<<<(N_NODES + 127) / 128, 256, SMEM_X>>>(hb, w2_root, w2_rel, b2, h0p, ha);

    // ---- pool + classify ----
    pool_kernel<<<N_GRAPHS, 64>>>(h0p, candA, candB, lin_w, lin_b, out);
}

// round 17
// speedup vs baseline: 1.5128x; 1.0664x over previous
#include <cuda_runtime.h>
#include <cuda_fp16.h>
#include <cstdint>
#include <cstdio>
#include <cstdlib>

#define N_NODES   50000
#define N_EDGES   1250000
#define EMBED     64
#define HIDDEN    64
#define NUM_REL   3
#define N_GRAPHS  512
#define N_CLASSES 2

#define NBINS (N_NODES * NUM_REL)            // 150000
#define SCAN_B 1024
#define SCAN_NB ((NBINS + SCAN_B - 1) / SCAN_B)   // 147

#define APF 68        // fp32 smem pitch: 64 + 4 pad

// ---------------- scratch ----------------
__device__ __align__(16) float  g_h0[N_NODES * 64];     // fp32 h (final layer -> pool)
__device__ __align__(16) __half g_h16a[N_NODES * 64];
__device__ __align__(16) __half g_h16b[N_NODES * 64];
__device__ __align__(16) __half g_agg16[NBINS * 64];    // fp16 agg (9.6 MB)
__device__ __align__(16) float  g_inv[NBINS];
__device__ int   g_cnt[NBINS];
__device__ int   g_off[NBINS + 1];
__device__ int   g_cur[NBINS];
__device__ int   g_bsum[SCAN_NB + 1];
__device__ int   g_eord[N_EDGES];
__device__ int   g_maxA;   // monotone across replays; deterministic
__device__ int   g_xsel;

// ---------------- init + classify (merged) ----------------
__global__ void init_classify_kernel(const int* __restrict__ A, int gsz) {
    int i = blockIdx.x * blockDim.x + threadIdx.x;
    if (i < NBINS) g_cnt[i] = 0;
    int m = 0;
    for (int j = i; j < N_NODES; j += gsz) m = max(m, A[j]);
    for (int o = 16; o > 0; o >>= 1) m = max(m, __shfl_down_sync(0xffffffffu, m, o));
    if ((threadIdx.x & 31) == 0 && m > 0) atomicMax(&g_maxA, m);
}

// ---------------- degree counts + CSR build ----------------
__global__ void count_kernel(const int* __restrict__ dst, const int* __restrict__ et) {
    int e = blockIdx.x * blockDim.x + threadIdx.x;
    if (e < N_EDGES)
        atomicAdd(&g_cnt[dst[e] * NUM_REL + et[e]], 1);
}

// scan1: block-local exclusive scan of cnt + inv computation (folded)
__global__ __launch_bounds__(SCAN_B)
void scan1_kernel() {
    __shared__ int wsum[32];
    int i = blockIdx.x * SCAN_B + threadIdx.x;
    int lane = threadIdx.x & 31, wid = threadIdx.x >> 5;
    int c = (i < NBINS) ? g_cnt[i] : 0;
    if (i < NBINS) g_inv[i] = 1.0f / (float)max(c, 1);
    int v = c;
#pragma unroll
    for (int o = 1; o < 32; o <<= 1) {
        int u = __shfl_up_sync(0xffffffffu, v, o);
        if (lane >= o) v += u;
    }
    if (lane == 31) wsum[wid] = v;
    __syncthreads();
    if (wid == 0) {
        int w = wsum[lane];
        int s = w;
#pragma unroll
        for (int o = 1; o < 32; o <<= 1) {
            int u = __shfl_up_sync(0xffffffffu, s, o);
            if (lane >= o) s += u;
        }
        wsum[lane] = s - w;
        if (lane == 31) g_bsum[blockIdx.x] = s;
    }
    __syncthreads();
    int excl = v - c + wsum[wid];
    if (i < NBINS) g_off[i] = excl;
}

// scan2: one-warp parallel scan of 147 block totals + setflag (folded)
__global__ void scan2_kernel() {
    int lane = threadIdx.x;               // 32 threads
    int base = lane * 5;
    int v[5];
    int s = 0;
#pragma unroll
    for (int j = 0; j < 5; j++) {
        int idx = base + j;
        v[j] = (idx < SCAN_NB) ? g_bsum[idx] : 0;
        s += v[j];
    }
    int excl = s;
#pragma unroll
    for (int o = 1; o < 32; o <<= 1) {
        int u = __shfl_up_sync(0xffffffffu, excl, o);
        if (lane >= o) excl += u;
    }
    excl -= s;                            // exclusive prefix of per-lane sums
    int run = excl;
#pragma unroll
    for (int j = 0; j < 5; j++) {
        int idx = base + j;
        if (idx < SCAN_NB) g_bsum[idx] = run;
        run += v[j];
    }
    if (lane == 31) {
        g_bsum[SCAN_NB] = run;            // total (lane 31 covers the tail)
        g_xsel = (g_maxA >= N_GRAPHS) ? 1 : 0;
    }
}

__global__ void scan3_kernel() {
    int i = blockIdx.x * blockDim.x + threadIdx.x;
    if (i < NBINS) {
        int off = g_off[i] + g_bsum[i / SCAN_B];
        g_off[i] = off;
        g_cur[i] = off;
    }
    if (i == 0) g_off[NBINS] = g_bsum[SCAN_NB];
}

__global__ void place_kernel(const int* __restrict__ src,
                             const int* __restrict__ dst,
                             const int* __restrict__ et) {
    int e = blockIdx.x * blockDim.x + threadIdx.x;
    if (e >= N_EDGES) return;
    int bin = dst[e] * NUM_REL + et[e];
    int pos = atomicAdd(&g_cur[bin], 1);
    g_eord[pos] = src[e];
}

// ---------------- embedding: fp32 table -> fp16 h ----------------
__global__ void embed_kernel(const int* __restrict__ candA, const int* __restrict__ candB,
                             const float* __restrict__ emb, __half* __restrict__ h16) {
    const int* x = g_xsel ? candA : candB;
    int i = blockIdx.x * blockDim.x + threadIdx.x;
    if (i >= N_NODES * 8) return;
    int n = i >> 3, q = i & 7;
    int tok = x[n];
    uint4 o = make_uint4(0, 0, 0, 0);
    if (tok != 0) {
        const float4* e4 = reinterpret_cast<const float4*>(emb);
        float4 f0 = e4[tok * 16 + q * 2];
        float4 f1 = e4[tok * 16 + q * 2 + 1];
        __half2 h0 = __floats2half2_rn(f0.x, f0.y);
        __half2 h1 = __floats2half2_rn(f0.z, f0.w);
        __half2 h2 = __floats2half2_rn(f1.x, f1.y);
        __half2 h3 = __floats2half2_rn(f1.z, f1.w);
        o.x = *reinterpret_cast<uint32_t*>(&h0);
        o.y = *reinterpret_cast<uint32_t*>(&h1);
        o.z = *reinterpret_cast<uint32_t*>(&h2);
        o.w = *reinterpret_cast<uint32_t*>(&h3);
    }
    reinterpret_cast<uint4*>(h16)[i] = o;
}

// ---------------- aggregation: CSR gather, unroll-4 for MLP ----------------
// 8 lanes/bin, 16B each; agg[bin] = inv * sum h16[src]
__global__ __launch_bounds__(256)
void agg_kernel(const __half* __restrict__ hin16) {
    int b = blockIdx.x * 32 + (threadIdx.x >> 3);
    if (b >= NBINS) return;
    int lane = threadIdx.x & 7;
    int i  = g_off[b];
    int s1 = g_off[b + 1];

    float acc[8] = {0.f, 0.f, 0.f, 0.f, 0.f, 0.f, 0.f, 0.f};
    const uint4* h4 = reinterpret_cast<const uint4*>(hin16);

    // 4-wide: 4 independent eord loads, then 4 independent gathers
    for (; i + 3 < s1; i += 4) {
        int e0 = g_eord[i];
        int e1 = g_eord[i + 1];
        int e2 = g_eord[i + 2];
        int e3 = g_eord[i + 3];
        uint4 v0 = h4[e0 * 8 + lane];
        uint4 v1 = h4[e1 * 8 + lane];
        uint4 v2 = h4[e2 * 8 + lane];
        uint4 v3 = h4[e3 * 8 + lane];
        const __half2* p0 = reinterpret_cast<const __half2*>(&v0);
        const __half2* p1 = reinterpret_cast<const __half2*>(&v1);
        const __half2* p2 = reinterpret_cast<const __half2*>(&v2);
        const __half2* p3 = reinterpret_cast<const __half2*>(&v3);
#pragma unroll
        for (int j = 0; j < 4; j++) {
            float2 f0 = __half22float2(p0[j]);
            float2 f1 = __half22float2(p1[j]);
            float2 f2 = __half22float2(p2[j]);
            float2 f3 = __half22float2(p3[j]);
            acc[2 * j]     += (f0.x + f1.x) + (f2.x + f3.x);
            acc[2 * j + 1] += (f0.y + f1.y) + (f2.y + f3.y);
        }
    }
    for (; i < s1; i++) {
        uint4 va = h4[g_eord[i] * 8 + lane];
        const __half2* pa = reinterpret_cast<const __half2*>(&va);
#pragma unroll
        for (int j = 0; j < 4; j++) {
            float2 fa = __half22float2(pa[j]);
            acc[2 * j]     += fa.x;
            acc[2 * j + 1] += fa.y;
        }
    }

    float iv = g_inv[b];
    uint4 outv;
    uint32_t* ow = &outv.x;
#pragma unroll
    for (int j = 0; j < 4; j++) {
        __half2 v = __floats2half2_rn(acc[2 * j] * iv, acc[2 * j + 1] * iv);
        ow[j] = *reinterpret_cast<uint32_t*>(&v);
    }
    reinterpret_cast<uint4*>(g_agg16)[b * 8 + lane] = outv;
}

// ---------------- tf32 helper ----------------
__device__ __forceinline__ uint32_t f2tf32(float f) {
    uint32_t r;
    asm("cvt.rna.tf32.f32 %0, %1;" : "=r"(r) : "f"(f));
    return r;
}

// ---------------- node transform: tf32 mma, A staged from fp16 ----------------
__global__ __launch_bounds__(256)
void transform_mma_kernel(const __half* __restrict__ hin16,
                          const float* __restrict__ wroot,
                          const float* __restrict__ wrel,
                          const float* __restrict__ bias,
                          float* __restrict__ hout32,      // nullptr -> skip fp32 store
                          __half* __restrict__ hout16) {
    extern __shared__ float sm[];
    float* As = sm;                 // 128 x APF (tf32)
    float* Ws = sm + 128 * APF;     // 64  x APF (tf32, transposed)

    int tid  = threadIdx.x;
    int lane = tid & 31, warp = tid >> 5;
    int wm = warp >> 1, wn = warp & 1;
    int g = lane >> 2, t = lane & 3;
    int n0 = blockIdx.x * 128;

    float c[2][4][4];
#pragma unroll
    for (int mt = 0; mt < 2; mt++)
#pragma unroll
        for (int nt = 0; nt < 4; nt++)
#pragma unroll
            for (int j = 0; j < 4; j++) c[mt][nt][j] = 0.f;

    const uint4* h4 = reinterpret_cast<const uint4*>(hin16);
    const uint4* a4 = reinterpret_cast<const uint4*>(g_agg16);

    for (int ch = 0; ch < 4; ch++) {
        __syncthreads();
#pragma unroll
        for (int it = 0; it < 4; it++) {
            int idx = it * 256 + tid;
            int row = idx >> 3, hq = idx & 7;
            int node = n0 + row;
            uint4 v = make_uint4(0, 0, 0, 0);
            if (node < N_NODES) {
                if (ch == 0) v = h4[node * 8 + hq];
                else         v = a4[(node * 3 + (ch - 1)) * 8 + hq];
            }
            const __half2* hp = reinterpret_cast<const __half2*>(&v);
            uint32_t* dst = reinterpret_cast<uint32_t*>(&As[row * APF + hq * 8]);
#pragma unroll
            for (int j = 0; j < 4; j++) {
                float2 f = __half22float2(hp[j]);
                dst[2 * j]     = f2tf32(f.x);
                dst[2 * j + 1] = f2tf32(f.y);
            }
        }
#pragma unroll
        for (int it = 0; it < 16; it++) {
            int idx = it * 256 + tid;
            int n = idx >> 6, kk = idx & 63;
            float w;
            if (ch == 0) w = wroot[kk * 64 + n];
            else         w = wrel[((ch - 1) * 64 + kk) * 64 + n];
            reinterpret_cast<uint32_t*>(Ws)[n * APF + kk] = f2tf32(w);
        }
        __syncthreads();

#pragma unroll
        for (int ks = 0; ks < 8; ks++) {
            int kk = ks * 8;
            uint32_t a[2][4], b[4][2];
            const uint32_t* Asu = reinterpret_cast<const uint32_t*>(As);
            const uint32_t* Wsu = reinterpret_cast<const uint32_t*>(Ws);
#pragma unroll
            for (int mt = 0; mt < 2; mt++) {
                int r0 = wm * 32 + mt * 16 + g;
                a[mt][0] = Asu[r0 * APF + kk + t];
                a[mt][1] = Asu[(r0 + 8) * APF + kk + t];
                a[mt][2] = Asu[r0 * APF + kk + t + 4];
                a[mt][3] = Asu[(r0 + 8) * APF + kk + t + 4];
            }
#pragma unroll
            for (int nt = 0; nt < 4; nt++) {
                int cN = wn * 32 + nt * 8 + g;
                b[nt][0] = Wsu[cN * APF + kk + t];
                b[nt][1] = Wsu[cN * APF + kk + t + 4];
            }
#pragma unroll
            for (int mt = 0; mt < 2; mt++)
#pragma unroll
                for (int nt = 0; nt < 4; nt++)
                    asm volatile(
                        "mma.sync.aligned.m16n8k8.row.col.f32.tf32.tf32.f32 "
                        "{%0,%1,%2,%3}, {%4,%5,%6,%7}, {%8,%9}, {%0,%1,%2,%3};"
                        : "+f"(c[mt][nt][0]), "+f"(c[mt][nt][1]),
                          "+f"(c[mt][nt][2]), "+f"(c[mt][nt][3])
                        : "r"(a[mt][0]), "r"(a[mt][1]), "r"(a[mt][2]), "r"(a[mt][3]),
                          "r"(b[nt][0]), "r"(b[nt][1]));
        }
    }

#pragma unroll
    for (int nt = 0; nt < 4; nt++) {
        int col = wn * 32 + nt * 8 + t * 2;
        float bx = bias[col], by = bias[col + 1];
#pragma unroll
        for (int mt = 0; mt < 2; mt++) {
            int r0 = n0 + wm * 32 + mt * 16 + g;
            if (r0 < N_NODES) {
                float vx = fmaxf(c[mt][nt][0] + bx, 0.f);
                float vy = fmaxf(c[mt][nt][1] + by, 0.f);
                if (hout32)
                    *reinterpret_cast<float2*>(&hout32[r0 * 64 + col]) = make_float2(vx, vy);
                __half2 hv = __floats2half2_rn(vx, vy);
                *reinterpret_cast<__half2*>(&hout16[r0 * 64 + col]) = hv;
            }
            int r1 = r0 + 8;
            if (r1 < N_NODES) {
                float vx = fmaxf(c[mt][nt][2] + bx, 0.f);
                float vy = fmaxf(c[mt][nt][3] + by, 0.f);
                if (hout32)
                    *reinterpret_cast<float2*>(&hout32[r1 * 64 + col]) = make_float2(vx, vy);
                __half2 hv = __floats2half2_rn(vx, vy);
                *reinterpret_cast<__half2*>(&hout16[r1 * 64 + col]) = hv;
            }
        }
    }
}

// ---------------- pooling + classifier (fp32 h) ----------------
__global__ void pool_kernel(const float* __restrict__ h,
                            const int* __restrict__ candA,
                            const int* __restrict__ candB,
                            const float* __restrict__ lin_w,
                            const float* __restrict__ lin_b,
                            float* __restrict__ out) {
    const int* batch = g_xsel ? candB : candA;
    int g = blockIdx.x;
    int f = threadIdx.x;
    __shared__ int bounds[2];
    __shared__ float mean_s[64];

    if (f < 2) {
        int v = g + f;
        int lo = 0, hi = N_NODES;
        while (lo < hi) {
            int m = (lo + hi) >> 1;
            if (batch[m] < v) lo = m + 1; else hi = m;
        }
        bounds[f] = lo;
    }
    __syncthreads();
    int s = bounds[0], e = bounds[1];

    float acc = 0.f;
    for (int i = s; i < e; i++) acc += h[i * 64 + f];
    float cnt = (float)(e - s);
    mean_s[f] = acc / fmaxf(cnt, 1.f);
    __syncthreads();

    if (f < N_CLASSES) {
        float o = lin_b[f];
#pragma unroll
        for (int k = 0; k < 64; k++) o += mean_s[k] * lin_w[k * N_CLASSES + f];
        out[g * N_CLASSES + f] = o;
    }
}

// ---------------- launch ----------------
extern "C" void kernel_launch(void* const* d_in, const int* in_sizes, int n_in,
                              void* d_out, int out_size) {
    float  *h0p = nullptr;
    __half *ha = nullptr, *hb = nullptr;
    cudaGetSymbolAddress((void**)&h0p, g_h0);
    cudaGetSymbolAddress((void**)&ha, g_h16a);
    cudaGetSymbolAddress((void**)&hb, g_h16b);
    if (!h0p || !ha || !hb) { fprintf(stderr, "HXH symbol addr failed\n"); abort(); }

    const void* pA50k = nullptr;  const void* pB50k = nullptr;
    const void* p_eidx = nullptr; const void* p_et = nullptr;
    const void* p_emb = nullptr;
    const void* p_rel[2]  = {nullptr, nullptr};
    const void* p_root[2] = {nullptr, nullptr};
    const void* p_b[2]    = {nullptr, nullptr};
    const void* p_linw = nullptr; const void* p_linb = nullptr;
    int n_rel = 0, n_root = 0, n_b = 0;

    for (int i = 0; i < n_in; i++) {
        int sz = in_sizes[i];
        const void* p = d_in[i];
        switch (sz) {
            case 2 * N_EDGES:       p_eidx = p; break;
            case N_EDGES:           p_et = p; break;
            case 50000 * EMBED:     p_emb = p; break;
            case NUM_REL * 64 * 64: if (n_rel < 2)  p_rel[n_rel++] = p;   break;
            case 64 * 64:           if (n_root < 2) p_root[n_root++] = p; break;
            case 64:                if (n_b < 2)    p_b[n_b++] = p;       break;
            case 64 * N_CLASSES:    p_linw = p; break;
            case N_CLASSES:         p_linb = p; break;
            case N_NODES:           if (!pA50k) pA50k = p; else pB50k = p; break;
            default: break;
        }
    }

    bool ok = pA50k && pB50k && p_eidx && p_et && p_emb &&
              n_rel == 2 && n_root == 2 && n_b == 2 && p_linw && p_linb;
    if (!ok) { fprintf(stderr, "HXH size-match failed\n"); fflush(stderr); abort(); }

    const int*   candA   = (const int*)pA50k;
    const int*   candB   = (const int*)pB50k;
    const int*   src     = (const int*)p_eidx;
    const int*   dst     = (const int*)p_eidx + N_EDGES;
    const int*   et      = (const int*)p_et;
    const float* emb     = (const float*)p_emb;
    const float* w1_rel  = (const float*)p_rel[0];
    const float* w2_rel  = (const float*)p_rel[1];
    const float* w1_root = (const float*)p_root[0];
    const float* w2_root = (const float*)p_root[1];
    const float* b1      = (const float*)p_b[0];
    const float* b2      = (const float*)p_b[1];
    const float* lin_w   = (const float*)p_linw;
    const float* lin_b   = (const float*)p_linb;
    float* out = (float*)d_out;

    const int T = 256;
    const int SMEM_X = (128 + 64) * APF * 4;   // 52224 B
    static bool attr_set = false;
    if (!attr_set) {
        cudaFuncSetAttribute(transform_mma_kernel,
                             cudaFuncAttributeMaxDynamicSharedMemorySize, SMEM_X);
        attr_set = true;
    }

    const int IC_G = (NBINS + T - 1) / T;
    init_classify_kernel<<<IC_G, T>>>(candA, IC_G * T);
    count_kernel<<<(N_EDGES + T - 1) / T, T>>>(dst, et);
    scan1_kernel<<<SCAN_NB, SCAN_B>>>();
    scan2_kernel<<<1, 32>>>();
    scan3_kernel<<<(NBINS + T - 1) / T, T>>>();
    place_kernel<<<(N_EDGES + T - 1) / T, T>>>(src, dst, et);

    // embedding -> h16a
    embed_kernel<<<(N_NODES * 8 + T - 1) / T, T>>>(candA, candB, emb, ha);

    // ---- layer 1 (no fp32 h needed) ----
    agg_kernel<<<(NBINS + 31) / 32, 256>>>(ha);
    transform_mma_kernel<<<(N_NODES + 127) / 128, 256, SMEM_X>>>(ha, w1_root, w1_rel, b1, nullptr, hb);

    // ---- layer 2 ----
    agg_kernel<<<(NBINS + 31) / 32, 256>>>(hb);
    transform_mma_kernel<<<(N_NODES + 127) / 128, 256, SMEM_X>>>(hb, w2_root, w2_rel, b2, h0p, ha);

    // ---- pool + classify ----
    pool_kernel<<<N_GRAPHS, 64>>>(h0p, candA, candB, lin_w, lin_b, out);
}